// round 10
// baseline (speedup 1.0000x reference)
#include <cuda_runtime.h>
#include <cuda_bf16.h>
#include <cstdint>

// ===========================================================================
// Tree-RNN round 9:
//  - leaf GEMM: exact R7 config (512 thr, 16 warps 4x4, warp tile 16x32,
//    BK=64, double-buffered cp.async), 3-term bf16 split.
//  - NEW: level 0 of the tree fused into the leaf epilogue (C tile -> smem,
//    fp32 pair-GEMM, h1 written directly; h0 never hits DRAM).
//  - remaining 12 levels: 256x16x4 -> 16x16x4 -> 1x16x4 + projection.
// ===========================================================================

// ----------------------------- scratch ------------------------------------
__device__ __nv_bfloat16 g_Bhi[128 * 4096];
__device__ __nv_bfloat16 g_Blo[128 * 4096];
__device__ float g_WTt[200 * 100];           // W k-major: WTt[k*100+n]
__device__ float g_h1[4096 * 100];           // level-0 output
__device__ float g_t1[256 * 100];
__device__ float g_t2[16 * 100];

// ----------------------------- helpers ------------------------------------
__device__ __forceinline__ void cp16(uint32_t saddr, const void* g) {
    asm volatile("cp.async.cg.shared.global [%0], [%1], 16;" :: "r"(saddr), "l"(g));
}
__device__ __forceinline__ void cp_commit() { asm volatile("cp.async.commit_group;"); }
__device__ __forceinline__ void cp_wait0()  { asm volatile("cp.async.wait_group 0;"); }

__device__ __forceinline__ void ldsm_x4(uint32_t& r0, uint32_t& r1, uint32_t& r2,
                                        uint32_t& r3, uint32_t addr) {
    asm volatile("ldmatrix.sync.aligned.m8n8.x4.shared.b16 {%0,%1,%2,%3}, [%4];"
                 : "=r"(r0), "=r"(r1), "=r"(r2), "=r"(r3) : "r"(addr));
}
__device__ __forceinline__ void mma16816(float* c, const uint32_t* a, const uint32_t* b) {
    asm volatile(
        "mma.sync.aligned.m16n8k16.row.col.f32.bf16.bf16.f32 "
        "{%0,%1,%2,%3}, {%4,%5,%6,%7}, {%8,%9}, {%0,%1,%2,%3};"
        : "+f"(c[0]), "+f"(c[1]), "+f"(c[2]), "+f"(c[3])
        : "r"(a[0]), "r"(a[1]), "r"(a[2]), "r"(a[3]), "r"(b[0]), "r"(b[1]));
}

__device__ __forceinline__ void split8(float4 a, float4 b, uint4& hv, uint4& lv) {
    __nv_bfloat162 h0 = __float22bfloat162_rn(make_float2(a.x, a.y));
    __nv_bfloat162 h1 = __float22bfloat162_rn(make_float2(a.z, a.w));
    __nv_bfloat162 h2 = __float22bfloat162_rn(make_float2(b.x, b.y));
    __nv_bfloat162 h3 = __float22bfloat162_rn(make_float2(b.z, b.w));
    float2 f0 = __bfloat1622float2(h0), f1 = __bfloat1622float2(h1);
    float2 f2 = __bfloat1622float2(h2), f3 = __bfloat1622float2(h3);
    __nv_bfloat162 l0 = __float22bfloat162_rn(make_float2(a.x - f0.x, a.y - f0.y));
    __nv_bfloat162 l1 = __float22bfloat162_rn(make_float2(a.z - f1.x, a.w - f1.y));
    __nv_bfloat162 l2 = __float22bfloat162_rn(make_float2(b.x - f2.x, b.y - f2.y));
    __nv_bfloat162 l3 = __float22bfloat162_rn(make_float2(b.z - f3.x, b.w - f3.y));
    hv = make_uint4(*(uint32_t*)&h0, *(uint32_t*)&h1, *(uint32_t*)&h2, *(uint32_t*)&h3);
    lv = make_uint4(*(uint32_t*)&l0, *(uint32_t*)&l1, *(uint32_t*)&l2, *(uint32_t*)&l3);
}

// ----------------------------- prep kernels --------------------------------
__global__ void prep_B(const float* __restrict__ We,
                       __nv_bfloat16* __restrict__ bhi, __nv_bfloat16* __restrict__ blo) {
    int idx = blockIdx.x * blockDim.x + threadIdx.x;
    if (idx >= 128 * 4096) return;
    int n = idx >> 12;
    float v = (n < 100) ? We[idx] : 0.0f;
    __nv_bfloat16 h = __float2bfloat16(v);
    bhi[idx] = h;
    blo[idx] = __float2bfloat16(v - __bfloat162float(h));
}
__global__ void prep_WTt(const float* __restrict__ W, float* __restrict__ dst) {
    int idx = blockIdx.x * blockDim.x + threadIdx.x;
    if (idx >= 200 * 100) return;
    int k = idx / 100, n = idx % 100;
    dst[idx] = W[n * 200 + k];
}

// ----------------------------- leaf GEMM + fused level 0 -------------------
// h0 tile = relu(A[64,4096] @ WeT + be) -> smem; h1 = relu(pairs @ W^T + b).
// BM=64, BN=128, BK=64; 16 warps 4(M)x4(N), warp tile 16x32. 144B rows.
#define AROWB     144
#define S_AHI     0
#define S_ALO     (64 * AROWB)
#define S_BHI     (2 * 64 * AROWB)
#define S_BLO     (S_BHI + 128 * AROWB)
#define LSTAGE    (S_BLO + 128 * AROWB)     // 55296
#define LEAF_SMEM (2 * LSTAGE)              // 110592
#define CPAD      104                       // C tile row stride (floats)

__global__ __launch_bounds__(512)
void leaf_gemm_mma(const float* __restrict__ A,
                   const __nv_bfloat16* __restrict__ Bhi,
                   const __nv_bfloat16* __restrict__ Blo,
                   const float* __restrict__ be,
                   const float* __restrict__ WTt,
                   const float* __restrict__ b,
                   float* __restrict__ H1) {
    extern __shared__ char smem[];
    const uint32_t sbase = (uint32_t)__cvta_generic_to_shared(smem);

    const int tid  = threadIdx.x;
    const int lane = tid & 31;
    const int wid  = tid >> 5;
    const int wm   = wid >> 2;       // 0..3 (16 rows each)
    const int wn   = wid & 3;        // 0..3 (32 cols each)
    const int row0 = blockIdx.x * 64;

    const int mat = lane >> 3, r8 = lane & 7;
    const uint32_t aoff =
        (uint32_t)((wm * 16 + (mat & 1) * 8 + r8) * AROWB + (mat >> 1) * 16);
    uint32_t boff[2];
#pragma unroll
    for (int nt = 0; nt < 2; nt++)
        boff[nt] = (uint32_t)((wn * 32 + nt * 16 + (mat >> 1) * 8 + r8) * AROWB +
                              (mat & 1) * 16);

    // A loads: 64 rows x 64 k fp32 -> 8 floats/thread
    const int ar  = tid >> 3;
    const int aks = tid & 7;
    const float* agp = A + (size_t)(row0 + ar) * 4096 + aks * 8;
    const uint32_t adof = (uint32_t)(ar * AROWB + aks * 16);

    const char* bhp = (const char*)Bhi;
    const char* blp = (const char*)Blo;

    float acc[4][4];
#pragma unroll
    for (int j = 0; j < 4; j++)
#pragma unroll
        for (int c = 0; c < 4; c++) acc[j][c] = 0.0f;

    float4 av0, av1;

    // ---- prologue: chunk 0 ----
    {
#pragma unroll
        for (int q = 0; q < 2; q++) {
            int idx = tid + q * 512;
            int brow = idx >> 3, seg = idx & 7;
            uint32_t dof = (uint32_t)(brow * AROWB + seg * 16);
            size_t gof = (size_t)brow * 8192 + seg * 16;
            cp16(sbase + S_BHI + dof, bhp + gof);
            cp16(sbase + S_BLO + dof, blp + gof);
        }
        cp_commit();
        av0 = *(const float4*)(agp);
        av1 = *(const float4*)(agp + 4);
        uint4 hv, lv;
        split8(av0, av1, hv, lv);
        *(uint4*)(smem + S_AHI + adof) = hv;
        *(uint4*)(smem + S_ALO + adof) = lv;
    }

    for (int i = 0; i < 64; i++) {
        const int s = i & 1;
        const uint32_t st = sbase + s * LSTAGE;
        const uint32_t nst = sbase + (s ^ 1) * LSTAGE;
        char* nst_gen = smem + (s ^ 1) * LSTAGE;

        cp_wait0();          // B chunk i resident
        __syncthreads();     // A chunk i visible; stage s^1 free

        if (i < 63) {
            const size_t kb = (size_t)(i + 1) * 128;  // bytes along K
#pragma unroll
            for (int q = 0; q < 2; q++) {
                int idx = tid + q * 512;
                int brow = idx >> 3, seg = idx & 7;
                uint32_t dof = (uint32_t)(brow * AROWB + seg * 16);
                size_t gof = (size_t)brow * 8192 + kb + seg * 16;
                cp16(nst + S_BHI + dof, bhp + gof);
                cp16(nst + S_BLO + dof, blp + gof);
            }
            cp_commit();
            const float* ap = agp + (size_t)(i + 1) * 64;
            av0 = *(const float4*)(ap);
            av1 = *(const float4*)(ap + 4);
        }

        // ---- compute chunk i: 4 x k16 ----
#pragma unroll
        for (int kk = 0; kk < 4; kk++) {
            const uint32_t kb = (uint32_t)(kk * 32);
            uint32_t ah[4], al[4], bh[2][4], bl[2][4];
            ldsm_x4(ah[0], ah[1], ah[2], ah[3], st + S_AHI + aoff + kb);
            ldsm_x4(al[0], al[1], al[2], al[3], st + S_ALO + aoff + kb);
#pragma unroll
            for (int nt = 0; nt < 2; nt++) {
                ldsm_x4(bh[nt][0], bh[nt][1], bh[nt][2], bh[nt][3],
                        st + S_BHI + boff[nt] + kb);
                ldsm_x4(bl[nt][0], bl[nt][1], bl[nt][2], bl[nt][3],
                        st + S_BLO + boff[nt] + kb);
            }
#pragma unroll
            for (int j = 0; j < 4; j++) {
                const int nt = j >> 1, p = (j & 1) * 2;
                uint32_t bhr[2] = {bh[nt][p], bh[nt][p + 1]};
                uint32_t blr[2] = {bl[nt][p], bl[nt][p + 1]};
                mma16816(acc[j], ah, bhr);   // hi*hi
                mma16816(acc[j], ah, blr);   // hi*lo
                mma16816(acc[j], al, bhr);   // lo*hi
            }
        }

        // ---- convert + STS A chunk i+1 into stage s^1 ----
        if (i < 63) {
            uint4 hv, lv;
            split8(av0, av1, hv, lv);
            *(uint4*)(nst_gen + S_AHI + adof) = hv;
            *(uint4*)(nst_gen + S_ALO + adof) = lv;
        }
    }

    // ---- epilogue A: bias + relu -> smem C tile (64 x CPAD fp32) ----
    // Cs occupies stage-0 region (26.6 KB); last compute used stage 1, and the
    // top-of-iter-63 __syncthreads guarantees no warp still reads stage 0.
    float* Cs = (float*)smem;
    {
        const int row = wm * 16 + (lane >> 2);
#pragma unroll
        for (int j = 0; j < 4; j++) {
            const int col = wn * 32 + j * 8 + (lane & 3) * 2;
#pragma unroll
            for (int c = 0; c < 4; c++) {
                const int rr = row + (c >> 1) * 8;
                const int cc = col + (c & 1);
                if (cc < 100)
                    Cs[rr * CPAD + cc] = fmaxf(acc[j][c] + __ldg(be + cc), 0.0f);
            }
        }
    }
    __syncthreads();

    // ---- epilogue B: level 0 (32 nodes from 32 adjacent row pairs) ----
    {
        const int n   = tid & 127;   // output feature
        const int grp = tid >> 7;    // 0..3
        if (n < 100) {
            const float bn = __ldg(b + n);
#pragma unroll
            for (int q = 0; q < 8; q++) {
                const int nd = grp + q * 4;       // 0..31
                const float* x0p = Cs + (2 * nd) * CPAD;
                const float* x1p = Cs + (2 * nd + 1) * CPAD;
                float s = 0.0f;
                for (int k0 = 0; k0 < 100; k0 += 4) {
                    float4 xa = *(const float4*)(x0p + k0);
                    float4 xb = *(const float4*)(x1p + k0);
                    s = fmaf(xa.x, __ldg(WTt + (k0 + 0) * 100 + n), s);
                    s = fmaf(xa.y, __ldg(WTt + (k0 + 1) * 100 + n), s);
                    s = fmaf(xa.z, __ldg(WTt + (k0 + 2) * 100 + n), s);
                    s = fmaf(xa.w, __ldg(WTt + (k0 + 3) * 100 + n), s);
                    s = fmaf(xb.x, __ldg(WTt + (100 + k0 + 0) * 100 + n), s);
                    s = fmaf(xb.y, __ldg(WTt + (100 + k0 + 1) * 100 + n), s);
                    s = fmaf(xb.z, __ldg(WTt + (100 + k0 + 2) * 100 + n), s);
                    s = fmaf(xb.w, __ldg(WTt + (100 + k0 + 3) * 100 + n), s);
                }
                H1[(size_t)(blockIdx.x * 32 + nd) * 100 + n] = fmaxf(s + bn, 0.0f);
            }
        }
    }
}

// ----------------------------- tree cascade --------------------------------
// 128 threads/block; W via __ldg; activations in smem.
template <int ROWS_IN, int NLEV>
__device__ __forceinline__ const float* tree_body(const float* __restrict__ in_rows,
                                                  const float* __restrict__ Wt,
                                                  const float* __restrict__ b,
                                                  float* bufA, float* bufB) {
    for (int i = threadIdx.x; i < ROWS_IN * 100; i += 128) bufA[i] = in_rows[i];
    __syncthreads();

    const float* cur = bufA;
    float* nxt = bufB;
    int m = ROWS_IN;
    const int n = threadIdx.x;
    const float bn = (n < 100) ? __ldg(b + n) : 0.0f;

#pragma unroll
    for (int l = 0; l < NLEV; l++) {
        const int mo = m >> 1;
        if (n < 100) {
            for (int rg = 0; rg < mo; rg += 8) {
                const int nr = (mo - rg < 8) ? (mo - rg) : 8;
                float acc[8];
#pragma unroll
                for (int c = 0; c < 8; c++) acc[c] = 0.0f;
                for (int k0 = 0; k0 < 200; k0 += 8) {
                    float w[8];
#pragma unroll
                    for (int j = 0; j < 8; j++) w[j] = __ldg(Wt + (k0 + j) * 100 + n);
#pragma unroll
                    for (int c = 0; c < 8; c++) {
                        if (c < nr) {
                            const float* xp = cur + (rg + c) * 200 + k0;
                            float4 x0 = *(const float4*)(xp);
                            float4 x1 = *(const float4*)(xp + 4);
                            acc[c] = fmaf(x0.x, w[0], acc[c]);
                            acc[c] = fmaf(x0.y, w[1], acc[c]);
                            acc[c] = fmaf(x0.z, w[2], acc[c]);
                            acc[c] = fmaf(x0.w, w[3], acc[c]);
                            acc[c] = fmaf(x1.x, w[4], acc[c]);
                            acc[c] = fmaf(x1.y, w[5], acc[c]);
                            acc[c] = fmaf(x1.z, w[6], acc[c]);
                            acc[c] = fmaf(x1.w, w[7], acc[c]);
                        }
                    }
                }
#pragma unroll
                for (int c = 0; c < 8; c++)
                    if (c < nr) nxt[(rg + c) * 100 + n] = fmaxf(acc[c] + bn, 0.0f);
            }
        }
        __syncthreads();
        const float* t = cur; cur = nxt; nxt = (float*)t;
        m = mo;
    }
    return cur;
}

__global__ __launch_bounds__(128)
void tree_stage1(const float* __restrict__ in, float* __restrict__ out,
                 const float* __restrict__ Wt, const float* __restrict__ b) {
    extern __shared__ float sm[];
    const float* res = tree_body<16, 4>(in + (size_t)blockIdx.x * 1600, Wt, b,
                                        sm, sm + 1600);
    if (threadIdx.x < 100) out[blockIdx.x * 100 + threadIdx.x] = res[threadIdx.x];
}
__global__ __launch_bounds__(128)
void tree_stage2(const float* __restrict__ in, float* __restrict__ out,
                 const float* __restrict__ Wt, const float* __restrict__ b) {
    extern __shared__ float sm[];
    const float* res = tree_body<16, 4>(in + (size_t)blockIdx.x * 1600, Wt, b,
                                        sm, sm + 1600);
    if (threadIdx.x < 100) out[blockIdx.x * 100 + threadIdx.x] = res[threadIdx.x];
}
__global__ __launch_bounds__(128)
void tree_stage3(const float* __restrict__ in, float* __restrict__ out,
                 const float* __restrict__ Wt, const float* __restrict__ b,
                 const float* __restrict__ Wp, const float* __restrict__ bp) {
    extern __shared__ float sm[];
    const float* res = tree_body<16, 4>(in, Wt, b, sm, sm + 1600);
    if (threadIdx.x < 64) {
        const int c = threadIdx.x >> 5;
        const int lane = threadIdx.x & 31;
        float s = 0.0f;
        for (int k = lane; k < 100; k += 32) s += __ldg(Wp + c * 100 + k) * res[k];
#pragma unroll
        for (int o = 16; o > 0; o >>= 1) s += __shfl_down_sync(0xffffffffu, s, o);
        if (lane == 0) out[c] = s + __ldg(bp + c);
    }
}

// ------------------------------ launch -------------------------------------
extern "C" void kernel_launch(void* const* d_in, const int* in_sizes, int n_in,
                              void* d_out, int out_size) {
    const float* leaf = (const float*)d_in[0];  // [8192, 4096]
    const float* We   = (const float*)d_in[1];  // [100, 4096]
    const float* be   = (const float*)d_in[2];  // [100]
    const float* W    = (const float*)d_in[3];  // [100, 200]
    const float* b    = (const float*)d_in[4];  // [100]
    const float* Wp   = (const float*)d_in[5];  // [2, 100]
    const float* bp   = (const float*)d_in[6];  // [2]
    float* out = (float*)d_out;

    __nv_bfloat16 *Bhi, *Blo;
    float *WTt, *h1, *t1, *t2;
    cudaGetSymbolAddress((void**)&Bhi, g_Bhi);
    cudaGetSymbolAddress((void**)&Blo, g_Blo);
    cudaGetSymbolAddress((void**)&WTt, g_WTt);
    cudaGetSymbolAddress((void**)&h1, g_h1);
    cudaGetSymbolAddress((void**)&t1, g_t1);
    cudaGetSymbolAddress((void**)&t2, g_t2);

    static int attr_set = 0;
    if (!attr_set) {
        cudaFuncSetAttribute(leaf_gemm_mma, cudaFuncAttributeMaxDynamicSharedMemorySize,
                             LEAF_SMEM);
        attr_set = 1;
    }

    prep_B<<<(128 * 4096 + 255) / 256, 256>>>(We, Bhi, Blo);
    prep_WTt<<<(200 * 100 + 255) / 256, 256>>>(W, WTt);

    leaf_gemm_mma<<<128, 512, LEAF_SMEM>>>(leaf, Bhi, Blo, be, WTt, b, h1);

    tree_stage1<<<256, 128, (1600 + 800) * 4>>>(h1, t1, WTt, b);
    tree_stage2<<<16, 128, (1600 + 800) * 4>>>(t1, t2, WTt, b);
    tree_stage3<<<1, 128, (1600 + 800) * 4>>>(t2, out, WTt, b, Wp, bp);
}

// round 12
// speedup vs baseline: 2.0122x; 2.0122x over previous
#include <cuda_runtime.h>
#include <cuda_bf16.h>
#include <cstdint>

// ===========================================================================
// Tree-RNN round 10:
//  - leaf GEMM: exact proven 512-thread config (16 warps 4x4, warp tile
//    16x32, BK=64, double-buffered cp.async), 3-term bf16 split. Untouched.
//  - tree: NEW feature-major formulation. X[feat][node] makes (left,right)
//    pair an adjacent float2 -> packed fma.rn.f32x2; W packed as per-k quads
//    (w_left[k], w_right[k], w_left[k+1], w_right[k+1]) -> 1 LDG.128 / 2 k.
//    Cascade 256x32x5 -> 8x32x5 -> 1x8x3 + projection.
// ===========================================================================

typedef unsigned long long ull;

// ----------------------------- scratch ------------------------------------
__device__ __nv_bfloat16 g_Bhi[128 * 4096];
__device__ __nv_bfloat16 g_Blo[128 * 4096];
__device__ float g_Wq[50 * 100 * 4];   // [kk][n][4] = {W[n][2kk],W[n][100+2kk],W[n][2kk+1],W[n][101+2kk]}
__device__ float g_h0[8192 * 100];     // leaf output, row-major
__device__ float g_T1[100 * 256];      // feature-major [feat][node]
__device__ float g_T2[100 * 8];

// ----------------------------- helpers ------------------------------------
__device__ __forceinline__ void cp16(uint32_t saddr, const void* g) {
    asm volatile("cp.async.cg.shared.global [%0], [%1], 16;" :: "r"(saddr), "l"(g));
}
__device__ __forceinline__ void cp_commit() { asm volatile("cp.async.commit_group;"); }
__device__ __forceinline__ void cp_wait0()  { asm volatile("cp.async.wait_group 0;"); }

__device__ __forceinline__ void ldsm_x4(uint32_t& r0, uint32_t& r1, uint32_t& r2,
                                        uint32_t& r3, uint32_t addr) {
    asm volatile("ldmatrix.sync.aligned.m8n8.x4.shared.b16 {%0,%1,%2,%3}, [%4];"
                 : "=r"(r0), "=r"(r1), "=r"(r2), "=r"(r3) : "r"(addr));
}
__device__ __forceinline__ void mma16816(float* c, const uint32_t* a, const uint32_t* b) {
    asm volatile(
        "mma.sync.aligned.m16n8k16.row.col.f32.bf16.bf16.f32 "
        "{%0,%1,%2,%3}, {%4,%5,%6,%7}, {%8,%9}, {%0,%1,%2,%3};"
        : "+f"(c[0]), "+f"(c[1]), "+f"(c[2]), "+f"(c[3])
        : "r"(a[0]), "r"(a[1]), "r"(a[2]), "r"(a[3]), "r"(b[0]), "r"(b[1]));
}

__device__ __forceinline__ void split8(float4 a, float4 b, uint4& hv, uint4& lv) {
    __nv_bfloat162 h0 = __float22bfloat162_rn(make_float2(a.x, a.y));
    __nv_bfloat162 h1 = __float22bfloat162_rn(make_float2(a.z, a.w));
    __nv_bfloat162 h2 = __float22bfloat162_rn(make_float2(b.x, b.y));
    __nv_bfloat162 h3 = __float22bfloat162_rn(make_float2(b.z, b.w));
    float2 f0 = __bfloat1622float2(h0), f1 = __bfloat1622float2(h1);
    float2 f2 = __bfloat1622float2(h2), f3 = __bfloat1622float2(h3);
    __nv_bfloat162 l0 = __float22bfloat162_rn(make_float2(a.x - f0.x, a.y - f0.y));
    __nv_bfloat162 l1 = __float22bfloat162_rn(make_float2(a.z - f1.x, a.w - f1.y));
    __nv_bfloat162 l2 = __float22bfloat162_rn(make_float2(b.x - f2.x, b.y - f2.y));
    __nv_bfloat162 l3 = __float22bfloat162_rn(make_float2(b.z - f3.x, b.w - f3.y));
    hv = make_uint4(*(uint32_t*)&h0, *(uint32_t*)&h1, *(uint32_t*)&h2, *(uint32_t*)&h3);
    lv = make_uint4(*(uint32_t*)&l0, *(uint32_t*)&l1, *(uint32_t*)&l2, *(uint32_t*)&l3);
}

__device__ __forceinline__ ull pack2(float lo, float hi) {
    ull r;
    asm("mov.b64 %0, {%1, %2};" : "=l"(r) : "f"(lo), "f"(hi));
    return r;
}
__device__ __forceinline__ void fma2(ull& d, ull a, ull b) {
    asm("fma.rn.f32x2 %0, %1, %2, %0;" : "+l"(d) : "l"(a), "l"(b));
}
__device__ __forceinline__ void unpack2(ull v, float& lo, float& hi) {
    asm("mov.b64 {%0, %1}, %2;" : "=f"(lo), "=f"(hi) : "l"(v));
}

// ----------------------------- prep kernels --------------------------------
__global__ void prep_B(const float* __restrict__ We,
                       __nv_bfloat16* __restrict__ bhi, __nv_bfloat16* __restrict__ blo) {
    int idx = blockIdx.x * blockDim.x + threadIdx.x;
    if (idx >= 128 * 4096) return;
    int n = idx >> 12;
    float v = (n < 100) ? We[idx] : 0.0f;
    __nv_bfloat16 h = __float2bfloat16(v);
    bhi[idx] = h;
    blo[idx] = __float2bfloat16(v - __bfloat162float(h));
}
// Wq[(kk*100+n)*4 + {0..3}] = {W[n][2kk], W[n][100+2kk], W[n][2kk+1], W[n][101+2kk]}
__global__ void prep_Wq(const float* __restrict__ W, float* __restrict__ Wq) {
    int idx = blockIdx.x * blockDim.x + threadIdx.x;   // 50*100
    if (idx >= 5000) return;
    int kk = idx / 100, n = idx % 100;
    float4 q;
    q.x = W[n * 200 + 2 * kk];
    q.y = W[n * 200 + 100 + 2 * kk];
    q.z = W[n * 200 + 2 * kk + 1];
    q.w = W[n * 200 + 101 + 2 * kk];
    *(float4*)(Wq + idx * 4) = q;
}

// ----------------------------- leaf GEMM (proven R7 config) ----------------
#define AROWB     144
#define S_AHI     0
#define S_ALO     (64 * AROWB)
#define S_BHI     (2 * 64 * AROWB)
#define S_BLO     (S_BHI + 128 * AROWB)
#define LSTAGE    (S_BLO + 128 * AROWB)     // 55296
#define LEAF_SMEM (2 * LSTAGE)              // 110592

__global__ __launch_bounds__(512)
void leaf_gemm_mma(const float* __restrict__ A,
                   const __nv_bfloat16* __restrict__ Bhi,
                   const __nv_bfloat16* __restrict__ Blo,
                   const float* __restrict__ bias,
                   float* __restrict__ C) {
    extern __shared__ char smem[];
    const uint32_t sbase = (uint32_t)__cvta_generic_to_shared(smem);

    const int tid  = threadIdx.x;
    const int lane = tid & 31;
    const int wid  = tid >> 5;
    const int wm   = wid >> 2;
    const int wn   = wid & 3;
    const int row0 = blockIdx.x * 64;

    const int mat = lane >> 3, r8 = lane & 7;
    const uint32_t aoff =
        (uint32_t)((wm * 16 + (mat & 1) * 8 + r8) * AROWB + (mat >> 1) * 16);
    uint32_t boff[2];
#pragma unroll
    for (int nt = 0; nt < 2; nt++)
        boff[nt] = (uint32_t)((wn * 32 + nt * 16 + (mat >> 1) * 8 + r8) * AROWB +
                              (mat & 1) * 16);

    const int ar  = tid >> 3;
    const int aks = tid & 7;
    const float* agp = A + (size_t)(row0 + ar) * 4096 + aks * 8;
    const uint32_t adof = (uint32_t)(ar * AROWB + aks * 16);

    const char* bhp = (const char*)Bhi;
    const char* blp = (const char*)Blo;

    float acc[4][4];
#pragma unroll
    for (int j = 0; j < 4; j++)
#pragma unroll
        for (int c = 0; c < 4; c++) acc[j][c] = 0.0f;

    float4 av0, av1;

    {
#pragma unroll
        for (int q = 0; q < 2; q++) {
            int idx = tid + q * 512;
            int brow = idx >> 3, seg = idx & 7;
            uint32_t dof = (uint32_t)(brow * AROWB + seg * 16);
            size_t gof = (size_t)brow * 8192 + seg * 16;
            cp16(sbase + S_BHI + dof, bhp + gof);
            cp16(sbase + S_BLO + dof, blp + gof);
        }
        cp_commit();
        av0 = *(const float4*)(agp);
        av1 = *(const float4*)(agp + 4);
        uint4 hv, lv;
        split8(av0, av1, hv, lv);
        *(uint4*)(smem + S_AHI + adof) = hv;
        *(uint4*)(smem + S_ALO + adof) = lv;
    }

    for (int i = 0; i < 64; i++) {
        const int s = i & 1;
        const uint32_t st = sbase + s * LSTAGE;
        const uint32_t nst = sbase + (s ^ 1) * LSTAGE;
        char* nst_gen = smem + (s ^ 1) * LSTAGE;

        cp_wait0();
        __syncthreads();

        if (i < 63) {
            const size_t kb = (size_t)(i + 1) * 128;
#pragma unroll
            for (int q = 0; q < 2; q++) {
                int idx = tid + q * 512;
                int brow = idx >> 3, seg = idx & 7;
                uint32_t dof = (uint32_t)(brow * AROWB + seg * 16);
                size_t gof = (size_t)brow * 8192 + kb + seg * 16;
                cp16(nst + S_BHI + dof, bhp + gof);
                cp16(nst + S_BLO + dof, blp + gof);
            }
            cp_commit();
            const float* ap = agp + (size_t)(i + 1) * 64;
            av0 = *(const float4*)(ap);
            av1 = *(const float4*)(ap + 4);
        }

#pragma unroll
        for (int kk = 0; kk < 4; kk++) {
            const uint32_t kb = (uint32_t)(kk * 32);
            uint32_t ah[4], al[4], bh[2][4], bl[2][4];
            ldsm_x4(ah[0], ah[1], ah[2], ah[3], st + S_AHI + aoff + kb);
            ldsm_x4(al[0], al[1], al[2], al[3], st + S_ALO + aoff + kb);
#pragma unroll
            for (int nt = 0; nt < 2; nt++) {
                ldsm_x4(bh[nt][0], bh[nt][1], bh[nt][2], bh[nt][3],
                        st + S_BHI + boff[nt] + kb);
                ldsm_x4(bl[nt][0], bl[nt][1], bl[nt][2], bl[nt][3],
                        st + S_BLO + boff[nt] + kb);
            }
#pragma unroll
            for (int j = 0; j < 4; j++) {
                const int nt = j >> 1, p = (j & 1) * 2;
                uint32_t bhr[2] = {bh[nt][p], bh[nt][p + 1]};
                uint32_t blr[2] = {bl[nt][p], bl[nt][p + 1]};
                mma16816(acc[j], ah, bhr);
                mma16816(acc[j], ah, blr);
                mma16816(acc[j], al, bhr);
            }
        }

        if (i < 63) {
            uint4 hv, lv;
            split8(av0, av1, hv, lv);
            *(uint4*)(nst_gen + S_AHI + adof) = hv;
            *(uint4*)(nst_gen + S_ALO + adof) = lv;
        }
    }

    const int row = row0 + wm * 16 + (lane >> 2);
#pragma unroll
    for (int j = 0; j < 4; j++) {
        const int col = wn * 32 + j * 8 + (lane & 3) * 2;
#pragma unroll
        for (int c = 0; c < 4; c++) {
            const int rr = row + (c >> 1) * 8;
            const int cc = col + (c & 1);
            if (cc < 100)
                C[(size_t)rr * 100 + cc] =
                    fmaxf(acc[j][c] + __ldg(bias + cc), 0.0f);
        }
    }
}

// ----------------------------- tree (feature-major, f32x2) -----------------
#define ST 36                         // X row stride in floats (even!)
#define TBUF (100 * ST)               // 3600 floats per buffer

// one level: Ys[n][j] = relu( sum_k wL[k]*Xs[k][2j] + wR[k]*Xs[k][2j+1] + bn )
__device__ __forceinline__ void level_fm(const float4* __restrict__ Wq4,
                                         float bn, int n,
                                         const float* __restrict__ Xs,
                                         float* __restrict__ Ys, int mo) {
    if (n < 100) {
        for (int jb = 0; jb < mo; jb += 16) {
            const int J = (mo - jb < 16) ? (mo - jb) : 16;
            ull acc[16];
#pragma unroll
            for (int j = 0; j < 16; j++) acc[j] = 0ull;
            for (int kk = 0; kk < 50; kk++) {
                float4 w = __ldg(Wq4 + kk * 100 + n);
                ull wA = pack2(w.x, w.y);   // k = 2kk
                ull wB = pack2(w.z, w.w);   // k = 2kk+1
                const ull* XA = (const ull*)(Xs + (2 * kk) * ST) + jb;
                const ull* XB = (const ull*)(Xs + (2 * kk + 1) * ST) + jb;
#pragma unroll
                for (int j = 0; j < 16; j++)
                    if (j < J) {
                        fma2(acc[j], wA, XA[j]);
                        fma2(acc[j], wB, XB[j]);
                    }
            }
#pragma unroll
            for (int j = 0; j < 16; j++)
                if (j < J) {
                    float lo, hi;
                    unpack2(acc[j], lo, hi);
                    Ys[n * ST + jb + j] = fmaxf(lo + hi + bn, 0.0f);
                }
        }
    }
    __syncthreads();
}

// stage1: 256 blocks x 32 leaf rows (row-major in) -> 5 levels -> T1[feat][blk]
__global__ __launch_bounds__(128)
void tree_stage1(const float* __restrict__ h0, float* __restrict__ T1,
                 const float* __restrict__ Wq, const float* __restrict__ b) {
    __shared__ float sm[2 * TBUF];
    const int n = threadIdx.x;
    const float bn = (n < 100) ? __ldg(b + n) : 0.0f;
    const float4* Wq4 = (const float4*)Wq;

    // transpose-load 32 rows x 100 feats -> X[feat][row]
    const float* in = h0 + (size_t)blockIdx.x * 3200;
    for (int i = n; i < 3200; i += 128) {
        int r = i / 100, f = i - r * 100;
        sm[f * ST + r] = in[i];
    }
    __syncthreads();

    float* X = sm;
    float* Y = sm + TBUF;
    int mo = 16;
#pragma unroll
    for (int l = 0; l < 5; l++) {
        level_fm(Wq4, bn, n, X, Y, mo);
        float* t = X; X = Y; Y = t;
        mo >>= 1;
    }
    if (n < 100) T1[n * 256 + blockIdx.x] = X[n * ST];
}

// stage2: 8 blocks x 32 cols of T1 (feature-major in) -> 5 levels -> T2[feat][blk]
__global__ __launch_bounds__(128)
void tree_stage2(const float* __restrict__ T1, float* __restrict__ T2,
                 const float* __restrict__ Wq, const float* __restrict__ b) {
    __shared__ float sm[2 * TBUF];
    const int n = threadIdx.x;
    const float bn = (n < 100) ? __ldg(b + n) : 0.0f;
    const float4* Wq4 = (const float4*)Wq;

    for (int i = n; i < 3200; i += 128) {
        int f = i >> 5, c = i & 31;
        sm[f * ST + c] = T1[f * 256 + blockIdx.x * 32 + c];
    }
    __syncthreads();

    float* X = sm;
    float* Y = sm + TBUF;
    int mo = 16;
#pragma unroll
    for (int l = 0; l < 5; l++) {
        level_fm(Wq4, bn, n, X, Y, mo);
        float* t = X; X = Y; Y = t;
        mo >>= 1;
    }
    if (n < 100) T2[n * 8 + blockIdx.x] = X[n * ST];
}

// stage3: 1 block, 8 cols -> 3 levels -> projection
__global__ __launch_bounds__(128)
void tree_stage3(const float* __restrict__ T2, float* __restrict__ out,
                 const float* __restrict__ Wq, const float* __restrict__ b,
                 const float* __restrict__ Wp, const float* __restrict__ bp) {
    __shared__ float sm[2 * TBUF];
    const int n = threadIdx.x;
    const float bn = (n < 100) ? __ldg(b + n) : 0.0f;
    const float4* Wq4 = (const float4*)Wq;

    for (int i = n; i < 800; i += 128) {
        int f = i >> 3, c = i & 7;
        sm[f * ST + c] = T2[i];
    }
    __syncthreads();

    float* X = sm;
    float* Y = sm + TBUF;
    int mo = 4;
#pragma unroll
    for (int l = 0; l < 3; l++) {
        level_fm(Wq4, bn, n, X, Y, mo);
        float* t = X; X = Y; Y = t;
        mo >>= 1;
    }
    if (n < 64) {
        const int c = n >> 5;
        const int lane = n & 31;
        float s = 0.0f;
        for (int k = lane; k < 100; k += 32) s += __ldg(Wp + c * 100 + k) * X[k * ST];
#pragma unroll
        for (int o = 16; o > 0; o >>= 1) s += __shfl_down_sync(0xffffffffu, s, o);
        if (lane == 0) out[c] = s + __ldg(bp + c);
    }
}

// ------------------------------ launch -------------------------------------
extern "C" void kernel_launch(void* const* d_in, const int* in_sizes, int n_in,
                              void* d_out, int out_size) {
    const float* leaf = (const float*)d_in[0];  // [8192, 4096]
    const float* We   = (const float*)d_in[1];  // [100, 4096]
    const float* be   = (const float*)d_in[2];  // [100]
    const float* W    = (const float*)d_in[3];  // [100, 200]
    const float* b    = (const float*)d_in[4];  // [100]
    const float* Wp   = (const float*)d_in[5];  // [2, 100]
    const float* bp   = (const float*)d_in[6];  // [2]
    float* out = (float*)d_out;

    __nv_bfloat16 *Bhi, *Blo;
    float *Wq, *h0, *T1, *T2;
    cudaGetSymbolAddress((void**)&Bhi, g_Bhi);
    cudaGetSymbolAddress((void**)&Blo, g_Blo);
    cudaGetSymbolAddress((void**)&Wq, g_Wq);
    cudaGetSymbolAddress((void**)&h0, g_h0);
    cudaGetSymbolAddress((void**)&T1, g_T1);
    cudaGetSymbolAddress((void**)&T2, g_T2);

    static int attr_set = 0;
    if (!attr_set) {
        cudaFuncSetAttribute(leaf_gemm_mma, cudaFuncAttributeMaxDynamicSharedMemorySize,
                             LEAF_SMEM);
        attr_set = 1;
    }

    prep_B<<<(128 * 4096 + 255) / 256, 256>>>(We, Bhi, Blo);
    prep_Wq<<<(5000 + 255) / 256, 256>>>(W, Wq);

    leaf_gemm_mma<<<128, 512, LEAF_SMEM>>>(leaf, Bhi, Blo, be, h0);

    tree_stage1<<<256, 128>>>(h0, T1, Wq, b);
    tree_stage2<<<8, 128>>>(T1, T2, Wq, b);
    tree_stage3<<<1, 128>>>(T2, out, Wq, b, Wp, bp);
}